// round 5
// baseline (speedup 1.0000x reference)
#include <cuda_runtime.h>
#include <math.h>
#include <stdint.h>

#define Bn 256
#define Tn 128
#define Fn 1024
#define Hn 512
#define IN1 1152
#define KSP 8          // k1 K-splits

__device__ float g_cp[KSP][Bn * Tn];  // k1 partials
__device__ float g_e[Bn * Fn];        // logits

__device__ __forceinline__ float tanh_fast(float x) {
    float y; asm("tanh.approx.f32 %0, %1;" : "=f"(y) : "f"(x)); return y;
}
__device__ __forceinline__ uint32_t f2tf32(float v) {
    uint32_t u; asm("cvt.rna.tf32.f32 %0, %1;" : "=r"(u) : "f"(v)); return u;
}
__device__ __forceinline__ void mma_tf32(float* d, const uint4& a, const uint2& b) {
    asm volatile(
        "mma.sync.aligned.m16n8k8.row.col.f32.tf32.tf32.f32 "
        "{%0,%1,%2,%3}, {%4,%5,%6,%7}, {%8,%9}, {%0,%1,%2,%3};"
        : "+f"(d[0]), "+f"(d[1]), "+f"(d[2]), "+f"(d[3])
        : "r"(a.x), "r"(a.y), "r"(a.z), "r"(a.w), "r"(b.x), "r"(b.y));
}

// ---------------------------------------------------------------------------
// k1: partial c[b,t]. grid (KSP=8, Bn/4=64) = 512 CTAs.
// CTA: 4 batches x 128 t x 128 k-slice.
// ---------------------------------------------------------------------------
#define BT1 4
__global__ __launch_bounds__(256) void k1_c(
    const float* __restrict__ h, const float* __restrict__ s,
    const float* __restrict__ W1, const float* __restrict__ b1) {
    __shared__ float hs[BT1 * 128];
    int tid = threadIdx.x;
    int ks = blockIdx.x;
    int b0 = blockIdx.y * BT1;

    if (tid < BT1 * 32) {                       // 128 float4 total
        int bb = tid >> 5, j4l = tid & 31;
        int jj = ks * 32 + j4l;                  // float4 idx within 1024-float hs
        float4 v;
        if (jj < 128) v = __ldg((const float4*)(h + (size_t)(b0 + bb) * Hn) + jj);
        else          v = __ldg((const float4*)(s + (size_t)(b0 + bb) * Hn) + (jj - 128));
        ((float4*)hs)[bb * 32 + j4l] = v;
    }
    __syncthreads();

    int t = tid >> 1, half = tid & 1;
    const float4* w4 = (const float4*)(W1 + (size_t)t * IN1 + Tn + ks * 128);
    float acc[BT1] = {0.f, 0.f, 0.f, 0.f};

    #pragma unroll 4
    for (int j = 0; j < 16; j++) {
        int idx4 = 2 * j + half;
        float4 w = __ldg(&w4[idx4]);
        #pragma unroll
        for (int bb = 0; bb < BT1; bb++) {
            float4 v = ((const float4*)hs)[bb * 32 + idx4];
            acc[bb] += w.x * v.x + w.y * v.y + w.z * v.z + w.w * v.w;
        }
    }
    #pragma unroll
    for (int bb = 0; bb < BT1; bb++)
        acc[bb] += __shfl_xor_sync(0xffffffffu, acc[bb], 1);
    if (!half) {
        float bias = (ks == 0) ? b1[t] : 0.f;
        #pragma unroll
        for (int bb = 0; bb < BT1; bb++)
            g_cp[ks][(b0 + bb) * Tn + t] = acc[bb] + bias;
    }
}

// ---------------------------------------------------------------------------
// k2: mma.sync tf32, double-buffered software pipeline.
// CTA = (f-tile 128, batch b). 8 warps = 2(M) x 4(N).
// Dynamic smem: Af[2][4096] u32 | Bf[2][4096] u32 = 64KB.
// ---------------------------------------------------------------------------
__global__ __launch_bounds__(256, 2) void k2_main(
    const float* __restrict__ x, const float* __restrict__ W1,
    const float* __restrict__ W2, const float* __restrict__ b2) {
    extern __shared__ uint32_t dyn[];
    // Af buf p at dyn + p*4096 ; Bf buf p at dyn + 8192 + p*4096
    __shared__ float c_s[Tn], w2_s[Tn];
    __shared__ float red2[2][128];

    int tid = threadIdx.x;
    int w = tid >> 5, lane = tid & 31;
    int wm = w >> 2, wn = w & 3;
    int g = lane >> 2, tq = lane & 3;
    int b  = blockIdx.y;
    int f0 = blockIdx.x * 128;

    if (tid < Tn) {
        float c = 0.f;
        #pragma unroll
        for (int k = 0; k < KSP; k++) c += g_cp[k][b * Tn + tid];
        c_s[tid]  = c;
        w2_s[tid] = __ldg(&W2[tid]);
    }

    float acc[4][4][4];
    #pragma unroll
    for (int i = 0; i < 4; i++)
        #pragma unroll
        for (int j = 0; j < 4; j++)
            #pragma unroll
            for (int r = 0; r < 4; r++) acc[i][j][r] = 0.f;

    const float* xb = x + (size_t)b * Tn * Fn;
    const float* r0 = W1 + (size_t)(w * 16 + g) * IN1;
    const float* r8 = r0 + 8 * IN1;
    const float* col0 = xb + f0 + (w * 2) * 8 + g;
    const float* col1 = col0 + 8;

    float bstg[16];

    // ---- helpers as macros over locals ----
#define LOAD_B_REGS(kc)                                                        \
    {                                                                          \
        _Pragma("unroll")                                                      \
        for (int ks = 0; ks < 4; ks++) {                                       \
            int k = (kc) + ks * 8 + tq;                                        \
            bstg[ks * 2 + 0]     = __ldg(col0 + (size_t)k * Fn);               \
            bstg[ks * 2 + 1]     = __ldg(col0 + (size_t)(k + 4) * Fn);         \
            bstg[8 + ks * 2 + 0] = __ldg(col1 + (size_t)k * Fn);               \
            bstg[8 + ks * 2 + 1] = __ldg(col1 + (size_t)(k + 4) * Fn);         \
        }                                                                      \
    }

#define STORE_B(q)                                                             \
    {                                                                          \
        uint32_t* Bf = dyn + 8192 + (q) * 4096;                                \
        _Pragma("unroll")                                                      \
        for (int jj = 0; jj < 2; jj++)                                         \
            _Pragma("unroll")                                                  \
            for (int ks = 0; ks < 4; ks++) {                                   \
                uint2 v;                                                       \
                v.x = f2tf32(bstg[jj * 8 + ks * 2 + 0]);                       \
                v.y = f2tf32(bstg[jj * 8 + ks * 2 + 1]);                       \
                *(uint2*)&Bf[((w * 2 + jj) * 4 + ks) * 64 + lane * 2] = v;     \
            }                                                                  \
    }

#define STAGE_A(kc, q)                                                         \
    {                                                                          \
        uint32_t* Af = dyn + (q) * 4096;                                       \
        _Pragma("unroll")                                                      \
        for (int ks = 0; ks < 4; ks++) {                                       \
            int c0 = (kc) + ks * 8 + tq;                                       \
            uint4 v;                                                           \
            v.x = f2tf32(__ldg(r0 + c0));                                      \
            v.y = f2tf32(__ldg(r8 + c0));                                      \
            v.z = f2tf32(__ldg(r0 + c0 + 4));                                  \
            v.w = f2tf32(__ldg(r8 + c0 + 4));                                  \
            *(uint4*)&Af[(w * 4 + ks) * 128 + lane * 4] = v;                   \
        }                                                                      \
    }

#define COMPUTE(p)                                                             \
    {                                                                          \
        const uint32_t* Af = dyn + (p) * 4096;                                 \
        const uint32_t* Bf = dyn + 8192 + (p) * 4096;                          \
        _Pragma("unroll")                                                      \
        for (int ks = 0; ks < 4; ks++) {                                       \
            uint4 a[4];                                                        \
            uint2 bbf[4];                                                      \
            _Pragma("unroll")                                                  \
            for (int i = 0; i < 4; i++)                                        \
                a[i] = *(const uint4*)&Af[((wm * 4 + i) * 4 + ks) * 128 + lane * 4]; \
            _Pragma("unroll")                                                  \
            for (int j = 0; j < 4; j++)                                        \
                bbf[j] = *(const uint2*)&Bf[((wn * 4 + j) * 4 + ks) * 64 + lane * 2]; \
            _Pragma("unroll")                                                  \
            for (int i = 0; i < 4; i++)                                        \
                _Pragma("unroll")                                              \
                for (int j = 0; j < 4; j++)                                    \
                    mma_tf32(acc[i][j], a[i], bbf[j]);                         \
        }                                                                      \
    }

    // ---- prologue: fill buffer 0 ----
    LOAD_B_REGS(0);
    STAGE_A(0, 0);
    STORE_B(0);
    __syncthreads();

    // ---- pipelined mainloop over 4 k-chunks ----
    #pragma unroll
    for (int kci = 0; kci < 4; kci++) {
        int p = kci & 1, q = p ^ 1;
        if (kci < 3) LOAD_B_REGS((kci + 1) * 32);   // LDGs in flight over compute
        COMPUTE(p);
        if (kci < 3) { STORE_B(q); STAGE_A((kci + 1) * 32, q); }
        __syncthreads();
    }

    // ---- epilogue: e[f] = b2 + sum_t W2[t] * tanh(D[t][f] + c[t]) ----
    float b2v = __ldg(&b2[0]);
    float es[4][2];
    #pragma unroll
    for (int j = 0; j < 4; j++) { es[j][0] = 0.f; es[j][1] = 0.f; }
    #pragma unroll
    for (int i = 0; i < 4; i++) {
        int t0 = (wm * 4 + i) * 16 + g;
        float c0 = c_s[t0],     w0 = w2_s[t0];
        float c1 = c_s[t0 + 8], w1 = w2_s[t0 + 8];
        #pragma unroll
        for (int j = 0; j < 4; j++) {
            es[j][0] += w0 * tanh_fast(acc[i][j][0] + c0)
                      + w1 * tanh_fast(acc[i][j][2] + c1);
            es[j][1] += w0 * tanh_fast(acc[i][j][1] + c0)
                      + w1 * tanh_fast(acc[i][j][3] + c1);
        }
    }
    #pragma unroll
    for (int j = 0; j < 4; j++)
        #pragma unroll
        for (int s2 = 0; s2 < 2; s2++) {
            float v = es[j][s2];
            v += __shfl_xor_sync(0xffffffffu, v, 4);
            v += __shfl_xor_sync(0xffffffffu, v, 8);
            v += __shfl_xor_sync(0xffffffffu, v, 16);
            es[j][s2] = v;
        }
    if (lane < 4) {
        #pragma unroll
        for (int j = 0; j < 4; j++) {
            int fl = (wn * 4 + j) * 8 + 2 * lane;
            red2[wm][fl]     = es[j][0];
            red2[wm][fl + 1] = es[j][1];
        }
    }
    __syncthreads();
    if (tid < 128)
        g_e[b * Fn + f0 + tid] = red2[0][tid] + red2[1][tid] + b2v;
}

// ---------------------------------------------------------------------------
// k3: softmax over f per batch
// ---------------------------------------------------------------------------
__global__ void k3_softmax(float* __restrict__ out) {
    __shared__ float smr[256];
    int b = blockIdx.x, tid = threadIdx.x;
    const float* eb = g_e + b * Fn;
    float v[4];
    float m = -1e30f;
    #pragma unroll
    for (int i = 0; i < 4; i++) { v[i] = eb[tid + i * 256]; m = fmaxf(m, v[i]); }
    smr[tid] = m; __syncthreads();
    for (int st = 128; st > 0; st >>= 1) {
        if (tid < st) smr[tid] = fmaxf(smr[tid], smr[tid + st]);
        __syncthreads();
    }
    m = smr[0];
    __syncthreads();
    float sum = 0.f;
    #pragma unroll
    for (int i = 0; i < 4; i++) { v[i] = __expf(v[i] - m); sum += v[i]; }
    smr[tid] = sum; __syncthreads();
    for (int st = 128; st > 0; st >>= 1) {
        if (tid < st) smr[tid] += smr[tid + st];
        __syncthreads();
    }
    float inv = 1.f / smr[0];
    #pragma unroll
    for (int i = 0; i < 4; i++) out[b * Fn + tid + i * 256] = v[i] * inv;
}

extern "C" void kernel_launch(void* const* d_in, const int* in_sizes, int n_in,
                              void* d_out, int out_size) {
    const float* h  = (const float*)d_in[0];
    const float* s  = (const float*)d_in[1];
    const float* x  = (const float*)d_in[2];
    const float* W1 = (const float*)d_in[3];
    const float* b1 = (const float*)d_in[4];
    const float* W2 = (const float*)d_in[5];
    const float* b2 = (const float*)d_in[6];
    float* out = (float*)d_out;

    static int init_done = 0;
    if (!init_done) {
        cudaFuncSetAttribute(k2_main, cudaFuncAttributeMaxDynamicSharedMemorySize,
                             16384 * (int)sizeof(uint32_t));
        init_done = 1;
    }

    dim3 g1(KSP, Bn / BT1);
    k1_c<<<g1, 256>>>(h, s, W1, b1);
    dim3 g2(Fn / 128, Bn);
    k2_main<<<g2, 256, 16384 * sizeof(uint32_t)>>>(x, W1, W2, b2);
    k3_softmax<<<Bn, 256>>>(out);
}

// round 6
// speedup vs baseline: 1.0284x; 1.0284x over previous
#include <cuda_runtime.h>
#include <math.h>
#include <stdint.h>

#define Bn 256
#define Tn 128
#define Fn 1024
#define Hn 512
#define IN1 1152
#define KSP 16         // k1 K-splits

__device__ float g_cp[KSP][Bn * Tn];  // k1 partials
__device__ float g_e[Bn * Fn];        // logits

__device__ __forceinline__ float tanh_fast(float x) {
    float y; asm("tanh.approx.f32 %0, %1;" : "=f"(y) : "f"(x)); return y;
}
__device__ __forceinline__ uint32_t f2tf32(float v) {
    uint32_t u; asm("cvt.rna.tf32.f32 %0, %1;" : "=r"(u) : "f"(v)); return u;
}
__device__ __forceinline__ uint32_t smem_u32(const void* p) {
    uint32_t a;
    asm("{ .reg .u64 t; cvta.to.shared.u64 t, %1; cvt.u32.u64 %0, t; }" : "=r"(a) : "l"(p));
    return a;
}
__device__ __forceinline__ void mma_tf32(float* d, const uint4& a, const uint2& b) {
    asm volatile(
        "mma.sync.aligned.m16n8k8.row.col.f32.tf32.tf32.f32 "
        "{%0,%1,%2,%3}, {%4,%5,%6,%7}, {%8,%9}, {%0,%1,%2,%3};"
        : "+f"(d[0]), "+f"(d[1]), "+f"(d[2]), "+f"(d[3])
        : "r"(a.x), "r"(a.y), "r"(a.z), "r"(a.w), "r"(b.x), "r"(b.y));
}
#define CP_ASYNC4(dst, src) \
    asm volatile("cp.async.ca.shared.global [%0], [%1], 4;" :: "r"(dst), "l"(src) : "memory")
#define CP_COMMIT()  asm volatile("cp.async.commit_group;" ::: "memory")
#define CP_WAIT(n)   asm volatile("cp.async.wait_group %0;" :: "n"(n) : "memory")

// ---------------------------------------------------------------------------
// k1: partial c[b,t]. grid (KSP=16, 64) = 1024 CTAs.
// CTA: 4 batches x 128 t x 64 k-slice.
// ---------------------------------------------------------------------------
#define BT1 4
__global__ __launch_bounds__(256) void k1_c(
    const float* __restrict__ h, const float* __restrict__ s,
    const float* __restrict__ W1, const float* __restrict__ b1) {
    __shared__ float hs[BT1 * 64];
    int tid = threadIdx.x;
    int ks = blockIdx.x;
    int b0 = blockIdx.y * BT1;

    if (tid < BT1 * 16) {                        // 64 float4 total
        int bb = tid >> 4, j4l = tid & 15;
        int jj = ks * 16 + j4l;                  // float4 idx within 1024-float hs
        float4 v;
        if (jj < 128) v = __ldg((const float4*)(h + (size_t)(b0 + bb) * Hn) + jj);
        else          v = __ldg((const float4*)(s + (size_t)(b0 + bb) * Hn) + (jj - 128));
        ((float4*)hs)[bb * 16 + j4l] = v;
    }
    __syncthreads();

    int t = tid >> 1, half = tid & 1;
    const float4* w4 = (const float4*)(W1 + (size_t)t * IN1 + Tn + ks * 64);
    float acc[BT1] = {0.f, 0.f, 0.f, 0.f};

    #pragma unroll
    for (int j = 0; j < 8; j++) {
        int idx4 = 2 * j + half;
        float4 w = __ldg(&w4[idx4]);
        #pragma unroll
        for (int bb = 0; bb < BT1; bb++) {
            float4 v = ((const float4*)hs)[bb * 16 + idx4];
            acc[bb] += w.x * v.x + w.y * v.y + w.z * v.z + w.w * v.w;
        }
    }
    #pragma unroll
    for (int bb = 0; bb < BT1; bb++)
        acc[bb] += __shfl_xor_sync(0xffffffffu, acc[bb], 1);
    if (!half) {
        float bias = (ks == 0) ? b1[t] : 0.f;
        #pragma unroll
        for (int bb = 0; bb < BT1; bb++)
            g_cp[ks][(b0 + bb) * Tn + t] = acc[bb] + bias;
    }
}

// ---------------------------------------------------------------------------
// k2: mma.sync tf32 with cp.async double-buffered B and fully-staged A.
// CTA = (f-tile 128, batch b). 8 warps = 2(M) x 4(N).
// Dynamic smem: A[4 chunks][4096] u32 (64KB) | B[2 bufs][4096] u32 (32KB).
// ---------------------------------------------------------------------------
#define A_OFF(kci) ((kci) * 4096)
#define B_OFF(q)   (16384 + (q) * 4096)

__global__ __launch_bounds__(256, 2) void k2_main(
    const float* __restrict__ x, const float* __restrict__ W1,
    const float* __restrict__ W2, const float* __restrict__ b2) {
    extern __shared__ uint32_t dyn[];
    __shared__ float c_s[Tn], w2_s[Tn];
    __shared__ float red2[2][128];

    int tid = threadIdx.x;
    int w = tid >> 5, lane = tid & 31;
    int wm = w >> 2, wn = w & 3;
    int g = lane >> 2, tq = lane & 3;
    int b  = blockIdx.y;
    int f0 = blockIdx.x * 128;

    uint32_t smbase = smem_u32(dyn);

    if (tid < Tn) {
        float c = 0.f;
        #pragma unroll
        for (int k = 0; k < KSP; k++) c += g_cp[k][b * Tn + tid];
        c_s[tid]  = c;
        w2_s[tid] = __ldg(&W2[tid]);
    }

    float acc[4][4][4];
    #pragma unroll
    for (int i = 0; i < 4; i++)
        #pragma unroll
        for (int j = 0; j < 4; j++)
            #pragma unroll
            for (int r = 0; r < 4; r++) acc[i][j][r] = 0.f;

    const float* xb = x + (size_t)b * Tn * Fn;
    const float* r0 = W1 + (size_t)(w * 16 + g) * IN1;
    const float* r8 = r0 + 8 * IN1;
    const float* col0 = xb + f0 + (w * 2) * 8 + g;
    const float* col1 = col0 + 8;

    // B chunk kc -> buffer q, raw fp32 bits (HW truncates to tf32)
#define ISSUE_B(kc, q)                                                         \
    {                                                                          \
        uint32_t bs = smbase + B_OFF(q) * 4;                                   \
        _Pragma("unroll")                                                      \
        for (int jj = 0; jj < 2; jj++) {                                       \
            const float* col = jj ? col1 : col0;                               \
            _Pragma("unroll")                                                  \
            for (int ks = 0; ks < 4; ks++) {                                   \
                int k = (kc) + ks * 8 + tq;                                    \
                uint32_t d0 = bs + ((((w * 2 + jj) * 4 + ks) * 64 + lane * 2) << 2); \
                CP_ASYNC4(d0,     col + (size_t)k * Fn);                       \
                CP_ASYNC4(d0 + 4, col + (size_t)(k + 4) * Fn);                 \
            }                                                                  \
        }                                                                      \
        CP_COMMIT();                                                           \
    }

#define COMPUTE(kci, p)                                                        \
    {                                                                          \
        const uint32_t* Af = dyn + A_OFF(kci);                                 \
        const uint32_t* Bf = dyn + B_OFF(p);                                   \
        _Pragma("unroll")                                                      \
        for (int ks = 0; ks < 4; ks++) {                                       \
            uint4 a[4];                                                        \
            uint2 bbf[4];                                                      \
            _Pragma("unroll")                                                  \
            for (int i = 0; i < 4; i++)                                        \
                a[i] = *(const uint4*)&Af[((wm * 4 + i) * 4 + ks) * 128 + lane * 4]; \
            _Pragma("unroll")                                                  \
            for (int j = 0; j < 4; j++)                                        \
                bbf[j] = *(const uint2*)&Bf[((wn * 4 + j) * 4 + ks) * 64 + lane * 2]; \
            _Pragma("unroll")                                                  \
            for (int i = 0; i < 4; i++)                                        \
                _Pragma("unroll")                                              \
                for (int j = 0; j < 4; j++)                                    \
                    mma_tf32(acc[i][j], a[i], bbf[j]);                         \
        }                                                                      \
    }

    // ---- prologue: start B chunks 0,1; stage A fully (cvt rna) meanwhile ----
    ISSUE_B(0, 0);
    ISSUE_B(32, 1);
    #pragma unroll
    for (int kci = 0; kci < 4; kci++) {
        uint32_t* Af = dyn + A_OFF(kci);
        #pragma unroll
        for (int ks = 0; ks < 4; ks++) {
            int c0 = kci * 32 + ks * 8 + tq;
            uint4 v;
            v.x = f2tf32(__ldg(r0 + c0));
            v.y = f2tf32(__ldg(r8 + c0));
            v.z = f2tf32(__ldg(r0 + c0 + 4));
            v.w = f2tf32(__ldg(r8 + c0 + 4));
            *(uint4*)&Af[(w * 4 + ks) * 128 + lane * 4] = v;
        }
    }

    // ---- mainloop ----
    #pragma unroll
    for (int kci = 0; kci < 4; kci++) {
        int p = kci & 1;
        if (kci < 3) { CP_WAIT(1); } else { CP_WAIT(0); }
        __syncthreads();                 // cp.async data + (iter0) A visible to all
        COMPUTE(kci, p);
        if (kci < 2) {
            __syncthreads();             // all readers done with buffer p
            ISSUE_B((kci + 2) * 32, p);  // refill buffer p
        }
    }

    // ---- epilogue: e[f] = b2 + sum_t W2[t] * tanh(D[t][f] + c[t]) ----
    float b2v = __ldg(&b2[0]);
    float es[4][2];
    #pragma unroll
    for (int j = 0; j < 4; j++) { es[j][0] = 0.f; es[j][1] = 0.f; }
    #pragma unroll
    for (int i = 0; i < 4; i++) {
        int t0 = (wm * 4 + i) * 16 + g;
        float c0 = c_s[t0],     w0 = w2_s[t0];
        float c1 = c_s[t0 + 8], w1 = w2_s[t0 + 8];
        #pragma unroll
        for (int j = 0; j < 4; j++) {
            es[j][0] += w0 * tanh_fast(acc[i][j][0] + c0)
                      + w1 * tanh_fast(acc[i][j][2] + c1);
            es[j][1] += w0 * tanh_fast(acc[i][j][1] + c0)
                      + w1 * tanh_fast(acc[i][j][3] + c1);
        }
    }
    #pragma unroll
    for (int j = 0; j < 4; j++)
        #pragma unroll
        for (int s2 = 0; s2 < 2; s2++) {
            float v = es[j][s2];
            v += __shfl_xor_sync(0xffffffffu, v, 4);
            v += __shfl_xor_sync(0xffffffffu, v, 8);
            v += __shfl_xor_sync(0xffffffffu, v, 16);
            es[j][s2] = v;
        }
    if (lane < 4) {
        #pragma unroll
        for (int j = 0; j < 4; j++) {
            int fl = (wn * 4 + j) * 8 + 2 * lane;
            red2[wm][fl]     = es[j][0];
            red2[wm][fl + 1] = es[j][1];
        }
    }
    __syncthreads();
    if (tid < 128)
        g_e[b * Fn + f0 + tid] = red2[0][tid] + red2[1][tid] + b2v;
}

// ---------------------------------------------------------------------------
// k3: softmax over f per batch
// ---------------------------------------------------------------------------
__global__ void k3_softmax(float* __restrict__ out) {
    __shared__ float smr[256];
    int b = blockIdx.x, tid = threadIdx.x;
    const float* eb = g_e + b * Fn;
    float v[4];
    float m = -1e30f;
    #pragma unroll
    for (int i = 0; i < 4; i++) { v[i] = eb[tid + i * 256]; m = fmaxf(m, v[i]); }
    smr[tid] = m; __syncthreads();
    for (int st = 128; st > 0; st >>= 1) {
        if (tid < st) smr[tid] = fmaxf(smr[tid], smr[tid + st]);
        __syncthreads();
    }
    m = smr[0];
    __syncthreads();
    float sum = 0.f;
    #pragma unroll
    for (int i = 0; i < 4; i++) { v[i] = __expf(v[i] - m); sum += v[i]; }
    smr[tid] = sum; __syncthreads();
    for (int st = 128; st > 0; st >>= 1) {
        if (tid < st) smr[tid] += smr[tid + st];
        __syncthreads();
    }
    float inv = 1.f / smr[0];
    #pragma unroll
    for (int i = 0; i < 4; i++) out[b * Fn + tid + i * 256] = v[i] * inv;
}

extern "C" void kernel_launch(void* const* d_in, const int* in_sizes, int n_in,
                              void* d_out, int out_size) {
    const float* h  = (const float*)d_in[0];
    const float* s  = (const float*)d_in[1];
    const float* x  = (const float*)d_in[2];
    const float* W1 = (const float*)d_in[3];
    const float* b1 = (const float*)d_in[4];
    const float* W2 = (const float*)d_in[5];
    const float* b2 = (const float*)d_in[6];
    float* out = (float*)d_out;

    static int init_done = 0;
    if (!init_done) {
        cudaFuncSetAttribute(k2_main, cudaFuncAttributeMaxDynamicSharedMemorySize,
                             24576 * (int)sizeof(uint32_t));
        init_done = 1;
    }

    dim3 g1(KSP, Bn / BT1);
    k1_c<<<g1, 256>>>(h, s, W1, b1);
    dim3 g2(Fn / 128, Bn);
    k2_main<<<g2, 256, 24576 * sizeof(uint32_t)>>>(x, W1, W2, b2);
    k3_softmax<<<Bn, 256>>>(out);
}

// round 7
// speedup vs baseline: 1.6518x; 1.6061x over previous
#include <cuda_runtime.h>
#include <math.h>
#include <stdint.h>

#define Bn 256
#define Tn 128
#define Fn 1024
#define Hn 512
#define IN1 1152
#define KSP 8          // k1 K-splits

__device__ float g_cp[KSP][Bn * Tn];  // k1 partials
__device__ float g_e[Bn * Fn];        // logits

__device__ __forceinline__ float tanh_fast(float x) {
    float y; asm("tanh.approx.f32 %0, %1;" : "=f"(y) : "f"(x)); return y;
}
// pack two f32 -> f16x2 (lo in low half)
__device__ __forceinline__ uint32_t pack_h2(float hi, float lo) {
    uint32_t d;
    asm("cvt.rn.f16x2.f32 %0, %1, %2;" : "=r"(d) : "f"(hi), "f"(lo));
    return d;
}
// D[16x8](f32) += A[16x16](f16) * B[16x8](f16)
__device__ __forceinline__ void mma_f16(float* d, const uint4& a, const uint2& b) {
    asm volatile(
        "mma.sync.aligned.m16n8k16.row.col.f32.f16.f16.f32 "
        "{%0,%1,%2,%3}, {%4,%5,%6,%7}, {%8,%9}, {%0,%1,%2,%3};"
        : "+f"(d[0]), "+f"(d[1]), "+f"(d[2]), "+f"(d[3])
        : "r"(a.x), "r"(a.y), "r"(a.z), "r"(a.w), "r"(b.x), "r"(b.y));
}

// ---------------------------------------------------------------------------
// k1: partial c[b,t]. grid (KSP=8, 64) = 512 CTAs (best measured config).
// CTA: 4 batches x 128 t x 128 k-slice.
// ---------------------------------------------------------------------------
#define BT1 4
__global__ __launch_bounds__(256) void k1_c(
    const float* __restrict__ h, const float* __restrict__ s,
    const float* __restrict__ W1, const float* __restrict__ b1) {
    __shared__ float hs[BT1 * 128];
    int tid = threadIdx.x;
    int ks = blockIdx.x;
    int b0 = blockIdx.y * BT1;

    if (tid < BT1 * 32) {
        int bb = tid >> 5, j4l = tid & 31;
        int jj = ks * 32 + j4l;
        float4 v;
        if (jj < 128) v = __ldg((const float4*)(h + (size_t)(b0 + bb) * Hn) + jj);
        else          v = __ldg((const float4*)(s + (size_t)(b0 + bb) * Hn) + (jj - 128));
        ((float4*)hs)[bb * 32 + j4l] = v;
    }
    __syncthreads();

    int t = tid >> 1, half = tid & 1;
    const float4* w4 = (const float4*)(W1 + (size_t)t * IN1 + Tn + ks * 128);
    float acc[BT1] = {0.f, 0.f, 0.f, 0.f};

    #pragma unroll 4
    for (int j = 0; j < 16; j++) {
        int idx4 = 2 * j + half;
        float4 w = __ldg(&w4[idx4]);
        #pragma unroll
        for (int bb = 0; bb < BT1; bb++) {
            float4 v = ((const float4*)hs)[bb * 32 + idx4];
            acc[bb] += w.x * v.x + w.y * v.y + w.z * v.z + w.w * v.w;
        }
    }
    #pragma unroll
    for (int bb = 0; bb < BT1; bb++)
        acc[bb] += __shfl_xor_sync(0xffffffffu, acc[bb], 1);
    if (!half) {
        float bias = (ks == 0) ? b1[t] : 0.f;
        #pragma unroll
        for (int bb = 0; bb < BT1; bb++)
            g_cp[ks][(b0 + bb) * Tn + t] = acc[bb] + bias;
    }
}

// ---------------------------------------------------------------------------
// k2: mma.sync fp16 m16n8k16, ALL of K=128 staged once (no chunking).
// CTA = (f-tile 128, batch b). 8 warps = 2(M) x 4(N); warp tile 64t x 32f.
// Dynamic smem (u32): A frags [mt 0..7][ks 0..7][128]  = 8192 (32KB)
//                     B frags [nt 0..15][ks 0..7][64]  = 8192 (32KB)
// Fragment layouts are producer-arranged; compute does only LDS.128/LDS.64.
// ---------------------------------------------------------------------------
__global__ __launch_bounds__(256, 2) void k2_main(
    const float* __restrict__ x, const float* __restrict__ W1,
    const float* __restrict__ W2, const float* __restrict__ b2) {
    extern __shared__ uint32_t dyn[];   // A at 0, B at 8192
    __shared__ float c_s[Tn], w2_s[Tn];
    __shared__ float red2[2][128];

    int tid = threadIdx.x;
    int w = tid >> 5, lane = tid & 31;
    int wm = w >> 2, wn = w & 3;
    int g = lane >> 2, tq = lane & 3;
    int b  = blockIdx.y;
    int f0 = blockIdx.x * 128;

    if (tid < Tn) {
        float c = 0.f;
        #pragma unroll
        for (int k = 0; k < KSP; k++) c += g_cp[k][b * Tn + tid];
        c_s[tid]  = c;
        w2_s[tid] = __ldg(&W2[tid]);
    }

    // ---- stage A: warp w handles mt = w (t rows w*16 .. w*16+15) ----
    {
        const float* r0 = W1 + (size_t)(w * 16 + g) * IN1;
        const float* r8 = r0 + 8 * IN1;
        #pragma unroll
        for (int ks = 0; ks < 8; ks++) {
            int c0 = ks * 16 + 2 * tq;
            float2 p00 = *(const float2*)(r0 + c0);       // (g,   c0..c0+1)
            float2 p10 = *(const float2*)(r8 + c0);       // (g+8, c0..c0+1)
            float2 p01 = *(const float2*)(r0 + c0 + 8);   // (g,   c0+8..9)
            float2 p11 = *(const float2*)(r8 + c0 + 8);   // (g+8, c0+8..9)
            uint4 v;
            v.x = pack_h2(p00.y, p00.x);
            v.y = pack_h2(p10.y, p10.x);
            v.z = pack_h2(p01.y, p01.x);
            v.w = pack_h2(p11.y, p11.x);
            *(uint4*)&dyn[(w * 8 + ks) * 128 + lane * 4] = v;
        }
    }
    // ---- stage B: warp w handles nt = 2w, 2w+1 (f cols nt*8 .. nt*8+7) ----
    {
        const float* xb = x + (size_t)b * Tn * Fn + f0;
        #pragma unroll
        for (int jj = 0; jj < 2; jj++) {
            int nt = w * 2 + jj;
            const float* col = xb + nt * 8 + g;
            #pragma unroll
            for (int ks = 0; ks < 8; ks++) {
                int k0 = ks * 16 + 2 * tq;
                float v00 = __ldg(col + (size_t)k0 * Fn);
                float v01 = __ldg(col + (size_t)(k0 + 1) * Fn);
                float v10 = __ldg(col + (size_t)(k0 + 8) * Fn);
                float v11 = __ldg(col + (size_t)(k0 + 9) * Fn);
                uint2 bv;
                bv.x = pack_h2(v01, v00);
                bv.y = pack_h2(v11, v10);
                *(uint2*)&dyn[8192 + (nt * 8 + ks) * 64 + lane * 2] = bv;
            }
        }
    }
    __syncthreads();

    // ---- compute: 8 k-steps x 4x4 mma ----
    float acc[4][4][4];
    #pragma unroll
    for (int i = 0; i < 4; i++)
        #pragma unroll
        for (int j = 0; j < 4; j++)
            #pragma unroll
            for (int r = 0; r < 4; r++) acc[i][j][r] = 0.f;

    #pragma unroll
    for (int ks = 0; ks < 8; ks++) {
        uint4 a[4];
        uint2 bf[4];
        #pragma unroll
        for (int i = 0; i < 4; i++)
            a[i] = *(const uint4*)&dyn[((wm * 4 + i) * 8 + ks) * 128 + lane * 4];
        #pragma unroll
        for (int j = 0; j < 4; j++)
            bf[j] = *(const uint2*)&dyn[8192 + ((wn * 4 + j) * 8 + ks) * 64 + lane * 2];
        #pragma unroll
        for (int i = 0; i < 4; i++)
            #pragma unroll
            for (int j = 0; j < 4; j++)
                mma_f16(acc[i][j], a[i], bf[j]);
    }

    // ---- epilogue: e[f] = b2 + sum_t W2[t] * tanh(D[t][f] + c[t]) ----
    float b2v = __ldg(&b2[0]);
    float es[4][2];
    #pragma unroll
    for (int j = 0; j < 4; j++) { es[j][0] = 0.f; es[j][1] = 0.f; }
    #pragma unroll
    for (int i = 0; i < 4; i++) {
        int t0 = (wm * 4 + i) * 16 + g;
        float c0 = c_s[t0],     w0 = w2_s[t0];
        float c1 = c_s[t0 + 8], w1 = w2_s[t0 + 8];
        #pragma unroll
        for (int j = 0; j < 4; j++) {
            es[j][0] += w0 * tanh_fast(acc[i][j][0] + c0)
                      + w1 * tanh_fast(acc[i][j][2] + c1);
            es[j][1] += w0 * tanh_fast(acc[i][j][1] + c0)
                      + w1 * tanh_fast(acc[i][j][3] + c1);
        }
    }
    #pragma unroll
    for (int j = 0; j < 4; j++)
        #pragma unroll
        for (int s2 = 0; s2 < 2; s2++) {
            float v = es[j][s2];
            v += __shfl_xor_sync(0xffffffffu, v, 4);
            v += __shfl_xor_sync(0xffffffffu, v, 8);
            v += __shfl_xor_sync(0xffffffffu, v, 16);
            es[j][s2] = v;
        }
    if (lane < 4) {
        #pragma unroll
        for (int j = 0; j < 4; j++) {
            int fl = (wn * 4 + j) * 8 + 2 * lane;
            red2[wm][fl]     = es[j][0];
            red2[wm][fl + 1] = es[j][1];
        }
    }
    __syncthreads();
    if (tid < 128)
        g_e[b * Fn + f0 + tid] = red2[0][tid] + red2[1][tid] + b2v;
}

// ---------------------------------------------------------------------------
// k3: softmax over f per batch
// ---------------------------------------------------------------------------
__global__ void k3_softmax(float* __restrict__ out) {
    __shared__ float smr[256];
    int b = blockIdx.x, tid = threadIdx.x;
    const float* eb = g_e + b * Fn;
    float v[4];
    float m = -1e30f;
    #pragma unroll
    for (int i = 0; i < 4; i++) { v[i] = eb[tid + i * 256]; m = fmaxf(m, v[i]); }
    smr[tid] = m; __syncthreads();
    for (int st = 128; st > 0; st >>= 1) {
        if (tid < st) smr[tid] = fmaxf(smr[tid], smr[tid + st]);
        __syncthreads();
    }
    m = smr[0];
    __syncthreads();
    float sum = 0.f;
    #pragma unroll
    for (int i = 0; i < 4; i++) { v[i] = __expf(v[i] - m); sum += v[i]; }
    smr[tid] = sum; __syncthreads();
    for (int st = 128; st > 0; st >>= 1) {
        if (tid < st) smr[tid] += smr[tid + st];
        __syncthreads();
    }
    float inv = 1.f / smr[0];
    #pragma unroll
    for (int i = 0; i < 4; i++) out[b * Fn + tid + i * 256] = v[i] * inv;
}

extern "C" void kernel_launch(void* const* d_in, const int* in_sizes, int n_in,
                              void* d_out, int out_size) {
    const float* h  = (const float*)d_in[0];
    const float* s  = (const float*)d_in[1];
    const float* x  = (const float*)d_in[2];
    const float* W1 = (const float*)d_in[3];
    const float* b1 = (const float*)d_in[4];
    const float* W2 = (const float*)d_in[5];
    const float* b2 = (const float*)d_in[6];
    float* out = (float*)d_out;

    static int init_done = 0;
    if (!init_done) {
        cudaFuncSetAttribute(k2_main, cudaFuncAttributeMaxDynamicSharedMemorySize,
                             16384 * (int)sizeof(uint32_t));
        init_done = 1;
    }

    dim3 g1(KSP, Bn / BT1);
    k1_c<<<g1, 256>>>(h, s, W1, b1);
    dim3 g2(Fn / 128, Bn);
    k2_main<<<g2, 256, 16384 * sizeof(uint32_t)>>>(x, W1, W2, b2);
    k3_softmax<<<Bn, 256>>>(out);
}